// round 2
// baseline (speedup 1.0000x reference)
#include <cuda_runtime.h>

#define NN 50000
#define EE 800000
#define ET (EE + NN)
#define HID 128
#define HEADS 8
#define NOUT 19
#define HF 152
#define SLOPE 0.2f
#define SEPS 1e-16f

// ---------------- scratch (device globals; no allocation) ----------------
__device__ float g_h[NN * HID];      // node features (updated in place)
__device__ float g_xp[NN * HF];      // per-block projected features
__device__ float g_u[NN * HF];       // layernorm output (GEMM2 input)
__device__ float g_als[NN * HEADS];  // (xp * a_src).sum per head
__device__ float g_ald[NN * HEADS];  // (xp * a_dst).sum per head
__device__ int g_off[NN + 1];        // CSR offsets (by dst)
__device__ int g_cur[NN];            // counts, then scatter cursors
__device__ int g_ssrc[ET];           // src node per CSR slot

// ---------------- embedding ----------------
__global__ void embed_k(const int* __restrict__ z, const float* __restrict__ emb) {
    int idx = blockIdx.x * blockDim.x + threadIdx.x;
    if (idx < NN * HID) {
        int n = idx / HID, c = idx % HID;
        g_h[idx] = emb[z[n] * HID + c];
    }
}

// ---------------- CSR build ----------------
__global__ void init_cnt_k() {
    int i = blockIdx.x * blockDim.x + threadIdx.x;
    if (i < NN) g_cur[i] = 1;  // self loop
}

__global__ void hist_k(const int* __restrict__ col) {
    int e = blockIdx.x * blockDim.x + threadIdx.x;
    if (e < EE) atomicAdd(&g_cur[col[e]], 1);
}

// single-block exclusive scan of g_cur -> g_off (and cursor init)
__global__ void scan_k() {
    __shared__ int wsum[32];
    __shared__ int s_carry;
    int t = threadIdx.x, lane = t & 31, wid = t >> 5;
    if (t == 0) s_carry = 0;
    __syncthreads();
    for (int base = 0; base < NN; base += 1024) {
        int i = base + t;
        int v = (i < NN) ? g_cur[i] : 0;
        int x = v;
#pragma unroll
        for (int d = 1; d < 32; d <<= 1) {
            int y = __shfl_up_sync(0xffffffffu, x, d);
            if (lane >= d) x += y;
        }
        if (lane == 31) wsum[wid] = x;
        __syncthreads();
        if (wid == 0) {
            int y = wsum[lane];
#pragma unroll
            for (int d = 1; d < 32; d <<= 1) {
                int z2 = __shfl_up_sync(0xffffffffu, y, d);
                if (lane >= d) y += z2;
            }
            wsum[lane] = y;
        }
        __syncthreads();
        int carry = s_carry;
        int excl = carry + (wid > 0 ? wsum[wid - 1] : 0) + x - v;
        if (i < NN) {
            g_off[i] = excl;
            g_cur[i] = excl;  // scatter cursor
        }
        int btot = wsum[31];
        __syncthreads();
        if (t == 0) s_carry = carry + btot;
        __syncthreads();
    }
    if (t == 0) g_off[NN] = s_carry;
}

__global__ void scatter_k(const int* __restrict__ row, const int* __restrict__ col) {
    int i = blockIdx.x * blockDim.x + threadIdx.x;
    if (i >= ET) return;
    int s, d;
    if (i < EE) { s = row[i]; d = col[i]; }
    else        { s = d = i - EE; }
    int p = atomicAdd(&g_cur[d], 1);
    g_ssrc[p] = s;
}

// ---------------- GEMM1: xp = h @ W  ([N,128] x [128,152]) ----------------
__global__ void gemm1_k(const float* __restrict__ W) {
    __shared__ float As[32][33];
    __shared__ float Ws[32][160];
    int t = threadIdx.x, lane = t & 31, ty = t >> 5;
    int row0 = blockIdx.x * 32;
    float acc[4][5];
#pragma unroll
    for (int i = 0; i < 4; i++)
#pragma unroll
        for (int j = 0; j < 5; j++) acc[i][j] = 0.f;

    for (int kk = 0; kk < HID; kk += 32) {
        for (int i = t; i < 32 * 32; i += 256) {
            int r = i >> 5, k = i & 31;
            int gr = row0 + r;
            As[r][k] = (gr < NN) ? g_h[gr * HID + kk + k] : 0.f;
        }
        for (int i = t; i < 32 * 160; i += 256) {
            int k = i / 160, c = i % 160;
            Ws[k][c] = (c < HF) ? W[(kk + k) * HF + c] : 0.f;
        }
        __syncthreads();
#pragma unroll
        for (int k = 0; k < 32; k++) {
            float wv[5];
#pragma unroll
            for (int j = 0; j < 5; j++) wv[j] = Ws[k][lane + 32 * j];
#pragma unroll
            for (int i4 = 0; i4 < 4; i4++) {
                float av = As[ty + 8 * i4][k];
#pragma unroll
                for (int j = 0; j < 5; j++) acc[i4][j] += av * wv[j];
            }
        }
        __syncthreads();
    }
#pragma unroll
    for (int i4 = 0; i4 < 4; i4++) {
        int r = row0 + ty + 8 * i4;
        if (r >= NN) continue;
#pragma unroll
        for (int j = 0; j < 5; j++) {
            int c = lane + 32 * j;
            if (c < HF) g_xp[r * HF + c] = acc[i4][j];
        }
    }
}

// ---------------- attention coefficients ----------------
__global__ void attn_k(const float* __restrict__ a_s, const float* __restrict__ a_d) {
    __shared__ float ss[HF], sd[HF];
    int t = threadIdx.x;
    if (t < HF) { ss[t] = a_s[t]; sd[t] = a_d[t]; }
    __syncthreads();
    int idx = blockIdx.x * blockDim.x + t;
    if (idx >= NN * HEADS) return;
    int n = idx / HEADS, h = idx % HEADS;
    const float* xr = g_xp + n * HF + h * NOUT;
    float vs = 0.f, vd = 0.f;
#pragma unroll
    for (int f = 0; f < NOUT; f++) {
        float x = xr[f];
        vs += x * ss[h * NOUT + f];
        vd += x * sd[h * NOUT + f];
    }
    g_als[idx] = vs;
    g_ald[idx] = vd;
}

// -------- aggregation: online softmax + message + layernorm (warp/dst) ----
__global__ void agg_k(const float* __restrict__ gb, const float* __restrict__ lg,
                      const float* __restrict__ lb) {
    int gw = (blockIdx.x * blockDim.x + threadIdx.x) >> 5;
    int lane = threadIdx.x & 31;
    if (gw >= NN) return;
    int d = gw;
    int beg = g_off[d], end = g_off[d + 1];

    float aldv = (lane < HEADS) ? g_ald[d * HEADS + lane] : 0.f;

    // single pass: running per-head max (lanes 0..7), rescaled sum + acc
    float mx = -1e30f;
    float ssum = 0.f;
    float acc[5] = {0.f, 0.f, 0.f, 0.f, 0.f};
    for (int e = beg; e < end; e++) {
        int s = g_ssrc[e];
        float als = (lane < HEADS) ? g_als[s * HEADS + lane] : 0.f;
        float ev = als + aldv;
        ev = ev > 0.f ? ev : SLOPE * ev;
        float mnew = fmaxf(mx, ev);
        float scale = __expf(mx - mnew);   // 1 if max unchanged; 0 on first edge
        float a = __expf(ev - mnew);
        ssum = ssum * scale + a;
        mx = mnew;
        const float* xr = g_xp + s * HF;
#pragma unroll
        for (int j = 0; j < 5; j++) {
            int f = lane + 32 * j;
            int hsrc = (f < HF) ? (f / NOUT) : 0;
            float ah = __shfl_sync(0xffffffffu, a, hsrc);
            float sch = __shfl_sync(0xffffffffu, scale, hsrc);
            if (f < HF) acc[j] = acc[j] * sch + ah * xr[f];
        }
    }

    // normalize + bias, then warp layernorm over 152 values
    float out[5];
    float lsum = 0.f;
#pragma unroll
    for (int j = 0; j < 5; j++) {
        int f = lane + 32 * j;
        int hsrc = (f < HF) ? (f / NOUT) : 0;
        float sh = __shfl_sync(0xffffffffu, ssum, hsrc);
        if (f < HF) {
            out[j] = acc[j] / (sh + SEPS) + gb[f];
            lsum += out[j];
        } else out[j] = 0.f;
    }
#pragma unroll
    for (int o = 16; o > 0; o >>= 1) lsum += __shfl_xor_sync(0xffffffffu, lsum, o);
    float mu = lsum / (float)HF;
    float lvar = 0.f;
#pragma unroll
    for (int j = 0; j < 5; j++) {
        int f = lane + 32 * j;
        if (f < HF) { float dv = out[j] - mu; lvar += dv * dv; }
    }
#pragma unroll
    for (int o = 16; o > 0; o >>= 1) lvar += __shfl_xor_sync(0xffffffffu, lvar, o);
    float inv = rsqrtf(lvar / (float)HF + 1e-5f);
#pragma unroll
    for (int j = 0; j < 5; j++) {
        int f = lane + 32 * j;
        if (f < HF) g_u[d * HF + f] = (out[j] - mu) * inv * lg[f] + lb[f];
    }
}

// ---------------- GEMM2: h_new = 2*h + u @ fW + fb ----------------
__global__ void gemm2_k(const float* __restrict__ fW, const float* __restrict__ fb,
                        float* dst) {
    __shared__ float Us[32][33];
    __shared__ float Ws[32][128];
    int t = threadIdx.x, lane = t & 31, ty = t >> 5;
    int row0 = blockIdx.x * 32;
    float* o = dst ? dst : g_h;
    float acc[4][4];
#pragma unroll
    for (int i = 0; i < 4; i++)
#pragma unroll
        for (int j = 0; j < 4; j++) acc[i][j] = 0.f;

    for (int kk = 0; kk < HF; kk += 32) {
        for (int i = t; i < 32 * 32; i += 256) {
            int r = i >> 5, k = i & 31;
            int gr = row0 + r, gk = kk + k;
            Us[r][k] = (gr < NN && gk < HF) ? g_u[gr * HF + gk] : 0.f;
        }
        for (int i = t; i < 32 * 128; i += 256) {
            int k = i >> 7, c = i & 127;
            int gk = kk + k;
            Ws[k][c] = (gk < HF) ? fW[gk * HID + c] : 0.f;
        }
        __syncthreads();
#pragma unroll
        for (int k = 0; k < 32; k++) {
            float wv[4];
#pragma unroll
            for (int j = 0; j < 4; j++) wv[j] = Ws[k][lane + 32 * j];
#pragma unroll
            for (int i4 = 0; i4 < 4; i4++) {
                float av = Us[ty + 8 * i4][k];
#pragma unroll
                for (int j = 0; j < 4; j++) acc[i4][j] += av * wv[j];
            }
        }
        __syncthreads();
    }
#pragma unroll
    for (int i4 = 0; i4 < 4; i4++) {
        int r = row0 + ty + 8 * i4;
        if (r >= NN) continue;
#pragma unroll
        for (int j = 0; j < 4; j++) {
            int c = lane + 32 * j;
            o[r * HID + c] = 2.f * g_h[r * HID + c] + acc[i4][j] + fb[c];
        }
    }
}

// ---------------- launch ----------------
extern "C" void kernel_launch(void* const* d_in, const int* in_sizes, int n_in,
                              void* d_out, int out_size) {
    const int* z = (const int*)d_in[0];
    // d_in[1] = pos (unused: edge_attr is dead in the reference)
    const int* ei = (const int*)d_in[2];
    const float* emb = (const float*)d_in[3];
    const float* gat_W = (const float*)d_in[4];
    const float* gat_b = (const float*)d_in[5];
    const float* a_src = (const float*)d_in[6];
    const float* a_dst = (const float*)d_in[7];
    const float* ln_g = (const float*)d_in[8];
    const float* ln_b = (const float*)d_in[9];
    const float* ff_W = (const float*)d_in[10];
    const float* ff_b = (const float*)d_in[11];
    float* outp = (float*)d_out;

    const int* row = ei;       // edge_index[0]
    const int* col = ei + EE;  // edge_index[1] (dst)

    embed_k<<<(NN * HID + 255) / 256, 256>>>(z, emb);
    init_cnt_k<<<(NN + 255) / 256, 256>>>();
    hist_k<<<(EE + 255) / 256, 256>>>(col);
    scan_k<<<1, 1024>>>();
    scatter_k<<<(ET + 255) / 256, 256>>>(row, col);

    for (int b = 0; b < 3; b++) {
        gemm1_k<<<(NN + 31) / 32, 256>>>(gat_W + b * HID * HF);
        attn_k<<<(NN * HEADS + 255) / 256, 256>>>(a_src + b * HF, a_dst + b * HF);
        agg_k<<<(NN + 7) / 8, 256>>>(gat_b + b * HF, ln_g + b * HF, ln_b + b * HF);
        gemm2_k<<<(NN + 31) / 32, 256>>>(ff_W + b * HF * HID, ff_b + b * HID,
                                         (b == 2) ? outp : nullptr);
    }
}

// round 3
// speedup vs baseline: 1.1955x; 1.1955x over previous
#include <cuda_runtime.h>

#define NN 50000
#define EE 800000
#define ET (EE + NN)
#define HID 128
#define HEADS 8
#define NOUT 19
#define HF 152
#define SLOPE 0.2f
#define SEPS 1e-16f
#define NB 49  // ceil(NN/1024)

// ---------------- scratch (device globals; no allocation) ----------------
__device__ float g_h[NN * HID];      // node features (updated in place)
__device__ float g_xp[NN * HF];      // per-block projected features
__device__ float g_u[NN * HF];       // layernorm output (GEMM2 input)
__device__ float g_als[NN * HEADS];  // (xp * a_src).sum per head
__device__ float g_ald[NN * HEADS];  // (xp * a_dst).sum per head
__device__ int g_off[NN + 1];        // CSR offsets (by dst)
__device__ int g_cur[NN];            // counts, then scatter cursors
__device__ int g_part[64];           // scan partials
__device__ int g_ssrc[ET];           // src node per CSR slot

// ---------------- embedding (warp per node, float4) + count init ----------
__global__ void embed_k(const int* __restrict__ z, const float* __restrict__ emb) {
    int idx = blockIdx.x * blockDim.x + threadIdx.x;  // NN*32 threads
    int n = idx >> 5, q = idx & 31;
    if (n >= NN) return;
    int zi = z[n];  // broadcast within warp
    const float4* src = (const float4*)(emb + zi * HID);
    ((float4*)(g_h + n * HID))[q] = src[q];
    if (q == 0) g_cur[n] = 1;  // self loop count
}

// ---------------- CSR build ----------------
__global__ void hist_k(const int* __restrict__ col) {
    int e = blockIdx.x * blockDim.x + threadIdx.x;
    if (e < EE) atomicAdd(&g_cur[col[e]], 1);
}

// block-local exclusive scan; block totals -> g_part
__global__ void scan1_k() {
    __shared__ int wsum[32];
    int t = threadIdx.x, lane = t & 31, wid = t >> 5;
    int i = blockIdx.x * 1024 + t;
    int v = (i < NN) ? g_cur[i] : 0;
    int x = v;
#pragma unroll
    for (int d = 1; d < 32; d <<= 1) {
        int y = __shfl_up_sync(0xffffffffu, x, d);
        if (lane >= d) x += y;
    }
    if (lane == 31) wsum[wid] = x;
    __syncthreads();
    if (wid == 0) {
        int y = wsum[lane];
#pragma unroll
        for (int d = 1; d < 32; d <<= 1) {
            int z2 = __shfl_up_sync(0xffffffffu, y, d);
            if (lane >= d) y += z2;
        }
        wsum[lane] = y;
    }
    __syncthreads();
    int excl = (wid > 0 ? wsum[wid - 1] : 0) + x - v;
    if (i < NN) g_off[i] = excl;
    if (t == 1023) g_part[blockIdx.x] = wsum[31];
}

// scan the NB partials (tiny)
__global__ void scan2_k() {
    if (threadIdx.x == 0) {
        int run = 0;
        for (int b = 0; b < NB; b++) {
            int v = g_part[b];
            g_part[b] = run;
            run += v;
        }
    }
}

// add partial prefix, init cursors
__global__ void scan3_k() {
    int i = blockIdx.x * blockDim.x + threadIdx.x;
    if (i < NN) {
        int v = g_off[i] + g_part[i >> 10];
        g_off[i] = v;
        g_cur[i] = v;
    }
    if (i == 0) g_off[NN] = ET;
}

__global__ void scatter_k(const int* __restrict__ row, const int* __restrict__ col) {
    int i = blockIdx.x * blockDim.x + threadIdx.x;
    if (i >= ET) return;
    int s, d;
    if (i < EE) { s = row[i]; d = col[i]; }
    else        { s = d = i - EE; }
    int p = atomicAdd(&g_cur[d], 1);
    g_ssrc[p] = s;
}

// ---------------- GEMM1: xp = h @ W  ([N,128] x [128,152]) ----------------
// tile 64 rows x 152 cols, 256 threads, 8x5 accs/thread
__global__ void gemm1_k(const float* __restrict__ W) {
    __shared__ float As[64][36];   // stride 36: rows 16B-aligned
    __shared__ float Ws[32][160];
    int t = threadIdx.x, lane = t & 31, ty = t >> 5;
    int row0 = blockIdx.x * 64;
    float acc[8][5];
#pragma unroll
    for (int i = 0; i < 8; i++)
#pragma unroll
        for (int j = 0; j < 5; j++) acc[i][j] = 0.f;

    for (int kk = 0; kk < HID; kk += 32) {
        // A: 64 rows x 32 k = 512 float4
        for (int i = t; i < 512; i += 256) {
            int r = i >> 3, q = i & 7;
            int gr = row0 + r;
            float4 v = (gr < NN) ? *(const float4*)(g_h + gr * HID + kk + 4 * q)
                                 : make_float4(0.f, 0.f, 0.f, 0.f);
            As[r][4 * q + 0] = v.x; As[r][4 * q + 1] = v.y;
            As[r][4 * q + 2] = v.z; As[r][4 * q + 3] = v.w;
        }
        // W: 32 k x 152 cols = 1216 float4 (cols 152..159 left stale; never stored)
        for (int i = t; i < 1216; i += 256) {
            int r = i / 38, q = i % 38;
            float4 v = *(const float4*)(W + (kk + r) * HF + 4 * q);
            Ws[r][4 * q + 0] = v.x; Ws[r][4 * q + 1] = v.y;
            Ws[r][4 * q + 2] = v.z; Ws[r][4 * q + 3] = v.w;
        }
        // zero pad cols 152..159 to avoid NaN garbage
        if (t < 32 * 8 / 32 * 4) {}  // no-op
        for (int i = t; i < 32 * 8; i += 256) {
            int r = i >> 3, c = 152 + (i & 7);
            Ws[r][c] = 0.f;
        }
        __syncthreads();
#pragma unroll
        for (int k = 0; k < 32; k++) {
            float wv[5];
#pragma unroll
            for (int j = 0; j < 5; j++) wv[j] = Ws[k][lane + 32 * j];
            float av[8];
#pragma unroll
            for (int i = 0; i < 8; i++) av[i] = As[ty + 8 * i][k];
#pragma unroll
            for (int i = 0; i < 8; i++)
#pragma unroll
                for (int j = 0; j < 5; j++) acc[i][j] += av[i] * wv[j];
        }
        __syncthreads();
    }
#pragma unroll
    for (int i = 0; i < 8; i++) {
        int r = row0 + ty + 8 * i;
        if (r >= NN) continue;
#pragma unroll
        for (int j = 0; j < 5; j++) {
            int c = lane + 32 * j;
            if (c < HF) g_xp[r * HF + c] = acc[i][j];
        }
    }
}

// ---------------- attention coefficients ----------------
__global__ void attn_k(const float* __restrict__ a_s, const float* __restrict__ a_d) {
    __shared__ float ss[HF], sd[HF];
    int t = threadIdx.x;
    if (t < HF) { ss[t] = a_s[t]; sd[t] = a_d[t]; }
    __syncthreads();
    int idx = blockIdx.x * blockDim.x + t;
    if (idx >= NN * HEADS) return;
    int n = idx / HEADS, h = idx % HEADS;
    const float* xr = g_xp + n * HF + h * NOUT;
    float vs = 0.f, vd = 0.f;
#pragma unroll
    for (int f = 0; f < NOUT; f++) {
        float x = xr[f];
        vs += x * ss[h * NOUT + f];
        vd += x * sd[h * NOUT + f];
    }
    g_als[idx] = vs;
    g_ald[idx] = vd;
}

// -------- aggregation: online softmax + message + layernorm (warp/dst) ----
__global__ void agg_k(const float* __restrict__ gb, const float* __restrict__ lg,
                      const float* __restrict__ lb) {
    int gw = (blockIdx.x * blockDim.x + threadIdx.x) >> 5;
    int lane = threadIdx.x & 31;
    if (gw >= NN) return;
    int d = gw;
    int beg = g_off[d], end = g_off[d + 1];

    float aldv = (lane < HEADS) ? g_ald[d * HEADS + lane] : 0.f;

    float mx = -1e30f;
    float ssum = 0.f;
    float acc[5] = {0.f, 0.f, 0.f, 0.f, 0.f};

    // prefetch first edge
    int s = g_ssrc[beg];
    float als = (lane < HEADS) ? g_als[s * HEADS + lane] : 0.f;
    const float* xr = g_xp + (long)s * HF;

    for (int e = beg; e < end; e++) {
        // issue feature loads for current edge early (independent of als)
        float xv[5];
#pragma unroll
        for (int j = 0; j < 5; j++) {
            int f = lane + 32 * j;
            xv[j] = (f < HF) ? xr[f] : 0.f;
        }
        // prefetch next edge's src + als
        int snext = 0; float alsnext = 0.f;
        if (e + 1 < end) {
            snext = g_ssrc[e + 1];
            alsnext = (lane < HEADS) ? g_als[snext * HEADS + lane] : 0.f;
        }
        // online softmax update
        float ev = als + aldv;
        ev = ev > 0.f ? ev : SLOPE * ev;
        float mnew = fmaxf(mx, ev);
        float scale = __expf(mx - mnew);
        float a = __expf(ev - mnew);
        ssum = ssum * scale + a;
        mx = mnew;
#pragma unroll
        for (int j = 0; j < 5; j++) {
            int f = lane + 32 * j;
            int hsrc = (f < HF) ? (f / NOUT) : 0;
            float ah = __shfl_sync(0xffffffffu, a, hsrc);
            float sch = __shfl_sync(0xffffffffu, scale, hsrc);
            acc[j] = acc[j] * sch + ah * xv[j];
        }
        s = snext; als = alsnext;
        xr = g_xp + (long)snext * HF;
    }

    // normalize + bias, then warp layernorm over 152 values
    float out[5];
    float lsum = 0.f;
#pragma unroll
    for (int j = 0; j < 5; j++) {
        int f = lane + 32 * j;
        int hsrc = (f < HF) ? (f / NOUT) : 0;
        float sh = __shfl_sync(0xffffffffu, ssum, hsrc);
        if (f < HF) {
            out[j] = acc[j] / (sh + SEPS) + gb[f];
            lsum += out[j];
        } else out[j] = 0.f;
    }
#pragma unroll
    for (int o = 16; o > 0; o >>= 1) lsum += __shfl_xor_sync(0xffffffffu, lsum, o);
    float mu = lsum / (float)HF;
    float lvar = 0.f;
#pragma unroll
    for (int j = 0; j < 5; j++) {
        int f = lane + 32 * j;
        if (f < HF) { float dv = out[j] - mu; lvar += dv * dv; }
    }
#pragma unroll
    for (int o = 16; o > 0; o >>= 1) lvar += __shfl_xor_sync(0xffffffffu, lvar, o);
    float inv = rsqrtf(lvar / (float)HF + 1e-5f);
#pragma unroll
    for (int j = 0; j < 5; j++) {
        int f = lane + 32 * j;
        if (f < HF) g_u[d * HF + f] = (out[j] - mu) * inv * lg[f] + lb[f];
    }
}

// ---------------- GEMM2: h_new = 2*h + u @ fW + fb ----------------
// tile 64 rows x 128 cols, 256 threads, 8x4 accs/thread, K=152 padded to 160
__global__ void gemm2_k(const float* __restrict__ fW, const float* __restrict__ fb,
                        float* dst) {
    __shared__ float Us[64][36];
    __shared__ float Ws[32][128];
    int t = threadIdx.x, lane = t & 31, ty = t >> 5;
    int row0 = blockIdx.x * 64;
    float* o = dst ? dst : g_h;
    float acc[8][4];
#pragma unroll
    for (int i = 0; i < 8; i++)
#pragma unroll
        for (int j = 0; j < 4; j++) acc[i][j] = 0.f;

    for (int kk = 0; kk < 160; kk += 32) {
        // U: 64 x 32 scalars (guard gk < 152)
        for (int i = t; i < 64 * 32; i += 256) {
            int r = i >> 5, k = i & 31;
            int gr = row0 + r, gk = kk + k;
            Us[r][k] = (gr < NN && gk < HF) ? g_u[gr * HF + gk] : 0.f;
        }
        // W: 32 x 128 = 1024 float4 (guard row gk < 152)
        for (int i = t; i < 1024; i += 256) {
            int r = i >> 5, q = i & 31;
            int gk = kk + r;
            float4 v = (gk < HF) ? *(const float4*)(fW + gk * HID + 4 * q)
                                 : make_float4(0.f, 0.f, 0.f, 0.f);
            Ws[r][4 * q + 0] = v.x; Ws[r][4 * q + 1] = v.y;
            Ws[r][4 * q + 2] = v.z; Ws[r][4 * q + 3] = v.w;
        }
        __syncthreads();
#pragma unroll
        for (int k = 0; k < 32; k++) {
            float wv[4];
#pragma unroll
            for (int j = 0; j < 4; j++) wv[j] = Ws[k][lane + 32 * j];
            float av[8];
#pragma unroll
            for (int i = 0; i < 8; i++) av[i] = Us[ty + 8 * i][k];
#pragma unroll
            for (int i = 0; i < 8; i++)
#pragma unroll
                for (int j = 0; j < 4; j++) acc[i][j] += av[i] * wv[j];
        }
        __syncthreads();
    }
#pragma unroll
    for (int i = 0; i < 8; i++) {
        int r = row0 + ty + 8 * i;
        if (r >= NN) continue;
#pragma unroll
        for (int j = 0; j < 4; j++) {
            int c = lane + 32 * j;
            o[r * HID + c] = 2.f * g_h[r * HID + c] + acc[i][j] + fb[c];
        }
    }
}

// ---------------- launch ----------------
extern "C" void kernel_launch(void* const* d_in, const int* in_sizes, int n_in,
                              void* d_out, int out_size) {
    const int* z = (const int*)d_in[0];
    // d_in[1] = pos (unused: edge_attr is dead in the reference)
    const int* ei = (const int*)d_in[2];
    const float* emb = (const float*)d_in[3];
    const float* gat_W = (const float*)d_in[4];
    const float* gat_b = (const float*)d_in[5];
    const float* a_src = (const float*)d_in[6];
    const float* a_dst = (const float*)d_in[7];
    const float* ln_g = (const float*)d_in[8];
    const float* ln_b = (const float*)d_in[9];
    const float* ff_W = (const float*)d_in[10];
    const float* ff_b = (const float*)d_in[11];
    float* outp = (float*)d_out;

    const int* row = ei;       // edge_index[0]
    const int* col = ei + EE;  // edge_index[1] (dst)

    embed_k<<<(NN * 32 + 255) / 256, 256>>>(z, emb);
    hist_k<<<(EE + 255) / 256, 256>>>(col);
    scan1_k<<<NB, 1024>>>();
    scan2_k<<<1, 32>>>();
    scan3_k<<<(NN + 255) / 256, 256>>>();
    scatter_k<<<(ET + 255) / 256, 256>>>(row, col);

    for (int b = 0; b < 3; b++) {
        gemm1_k<<<(NN + 63) / 64, 256>>>(gat_W + b * HID * HF);
        attn_k<<<(NN * HEADS + 255) / 256, 256>>>(a_src + b * HF, a_dst + b * HF);
        agg_k<<<(NN + 7) / 8, 256>>>(gat_b + b * HF, ln_g + b * HF, ln_b + b * HF);
        gemm2_k<<<(NN + 63) / 64, 256>>>(ff_W + b * HF * HID, ff_b + b * HID,
                                         (b == 2) ? outp : nullptr);
    }
}

// round 5
// speedup vs baseline: 1.4431x; 1.2071x over previous
#include <cuda_runtime.h>
#include <cuda_bf16.h>
#include <cstdint>

#define NN 50000
#define EE 800000
#define ET (EE + NN)
#define HID 128
#define HEADS 8
#define NOUT 19
#define HF 152
#define SLOPE 0.2f
#define SEPS 1e-16f
#define NB 49  // ceil(NN/1024)

// ================= scratch =================
__device__ float g_h[NN * HID];
__device__ float g_xp[NN * HF];
__device__ float g_u[NN * HF];
__device__ float g_als[NN * HEADS];
__device__ float g_ald[NN * HEADS];
__device__ float g_mx[NN * HEADS];
__device__ float g_siv[NN * HEADS];
__device__ int g_off[NN + 1];
__device__ int g_cur[NN];
__device__ int g_part[64];
__device__ int g_ssrc[ET];

__device__ __forceinline__ void split_bf16(float a, float b, uint32_t& hi, uint32_t& lo) {
    __nv_bfloat162 h2 = __floats2bfloat162_rn(a, b);
    float la = a - __bfloat162float(h2.x);
    float lb = b - __bfloat162float(h2.y);
    __nv_bfloat162 l2 = __floats2bfloat162_rn(la, lb);
    hi = *(uint32_t*)&h2;
    lo = *(uint32_t*)&l2;
}

__device__ __forceinline__ void mma_bf16(float* c, uint32_t a0, uint32_t a1, uint32_t a2,
                                         uint32_t a3, uint32_t b0, uint32_t b1) {
    asm volatile(
        "mma.sync.aligned.m16n8k16.row.col.f32.bf16.bf16.f32 "
        "{%0,%1,%2,%3}, {%4,%5,%6,%7}, {%8,%9}, {%0,%1,%2,%3};\n"
        : "+f"(c[0]), "+f"(c[1]), "+f"(c[2]), "+f"(c[3])
        : "r"(a0), "r"(a1), "r"(a2), "r"(a3), "r"(b0), "r"(b1));
}

// ================= setup kernels =================
__global__ void embed_k(const int* __restrict__ z, const float* __restrict__ emb) {
    int idx = blockIdx.x * blockDim.x + threadIdx.x;
    int n = idx >> 5, q = idx & 31;
    if (n >= NN) return;
    int zi = z[n];
    ((float4*)(g_h + n * HID))[q] = ((const float4*)(emb + zi * HID))[q];
    if (q == 0) g_cur[n] = 1;  // self loop
}

__global__ void hist_k(const int* __restrict__ col) {
    int e = blockIdx.x * blockDim.x + threadIdx.x;
    if (e < EE) atomicAdd(&g_cur[col[e]], 1);
}

__global__ void scan1_k() {
    __shared__ int wsum[32];
    int t = threadIdx.x, lane = t & 31, wid = t >> 5;
    int i = blockIdx.x * 1024 + t;
    int v = (i < NN) ? g_cur[i] : 0;
    int x = v;
#pragma unroll
    for (int d = 1; d < 32; d <<= 1) {
        int y = __shfl_up_sync(0xffffffffu, x, d);
        if (lane >= d) x += y;
    }
    if (lane == 31) wsum[wid] = x;
    __syncthreads();
    if (wid == 0) {
        int y = wsum[lane];
#pragma unroll
        for (int d = 1; d < 32; d <<= 1) {
            int z2 = __shfl_up_sync(0xffffffffu, y, d);
            if (lane >= d) y += z2;
        }
        wsum[lane] = y;
    }
    __syncthreads();
    int excl = (wid > 0 ? wsum[wid - 1] : 0) + x - v;
    if (i < NN) g_off[i] = excl;
    if (t == 1023) g_part[blockIdx.x] = wsum[31];
}

__global__ void scan2_k() {  // single warp scan of NB partials
    int t = threadIdx.x;
    int v0 = (t < NB) ? g_part[t] : 0;
    int v1 = (t + 32 < NB) ? g_part[t + 32] : 0;
    int s0 = v0;
#pragma unroll
    for (int d = 1; d < 32; d <<= 1) {
        int y = __shfl_up_sync(0xffffffffu, s0, d);
        if (t >= d) s0 += y;
    }
    int tot0 = __shfl_sync(0xffffffffu, s0, 31);
    int s1 = v1;
#pragma unroll
    for (int d = 1; d < 32; d <<= 1) {
        int y = __shfl_up_sync(0xffffffffu, s1, d);
        if (t >= d) s1 += y;
    }
    g_part[t] = s0 - v0;
    g_part[t + 32] = tot0 + s1 - v1;
}

__global__ void scan3_k() {
    int i = blockIdx.x * blockDim.x + threadIdx.x;
    if (i < NN) {
        int v = g_off[i] + g_part[i >> 10];
        g_off[i] = v;
        g_cur[i] = v;
    }
    if (i == 0) g_off[NN] = ET;
}

__global__ void scatter_k(const int* __restrict__ row, const int* __restrict__ col) {
    int i = blockIdx.x * blockDim.x + threadIdx.x;
    if (i >= ET) return;
    int s, d;
    if (i < EE) { s = row[i]; d = col[i]; }
    else        { s = d = i - EE; }
    int p = atomicAdd(&g_cur[d], 1);
    g_ssrc[p] = s;
}

// ============ GEMM1: xp[N,152] = h[N,128] @ W[128,152], mma.sync bf16 ======
// smem: A row stride 136 bf16 (272B), B row stride 136 bf16.
#define G1_ASTR 272
#define G1_AHI 0
#define G1_ALO (G1_AHI + 128 * G1_ASTR)            // 34816
#define G1_BHI (G1_ALO + 128 * G1_ASTR)            // 69632
#define G1_BLO (G1_BHI + 152 * G1_ASTR)            // 110976
#define G1_SMEM (G1_BLO + 152 * G1_ASTR)           // 152320

__global__ __launch_bounds__(256, 1) void gemm1_k(const float* __restrict__ W) {
    extern __shared__ char sm[];
    int t = threadIdx.x, lane = t & 31, wid = t >> 5;
    int row0 = blockIdx.x * 128;

    // ---- A fill: 128 rows x 64 col-pairs ----
    for (int i = t; i < 128 * 64; i += 256) {
        int r = i >> 6, cp = i & 63;
        int gr = row0 + r;
        float2 v = (gr < NN) ? *(const float2*)(g_h + (size_t)gr * HID + 2 * cp)
                             : make_float2(0.f, 0.f);
        uint32_t hi, lo;
        split_bf16(v.x, v.y, hi, lo);
        *(uint32_t*)(sm + G1_AHI + r * G1_ASTR + cp * 4) = hi;
        *(uint32_t*)(sm + G1_ALO + r * G1_ASTR + cp * 4) = lo;
    }
    // ---- B fill: Bs[n][kp] = (W[2kp][n], W[2kp+1][n]) ----
    for (int i = t; i < 64 * HF; i += 256) {
        int kp = i / HF, n = i % HF;
        float w0 = W[(2 * kp) * HF + n];
        float w1 = W[(2 * kp + 1) * HF + n];
        uint32_t hi, lo;
        split_bf16(w0, w1, hi, lo);
        *(uint32_t*)(sm + G1_BHI + n * G1_ASTR + kp * 4) = hi;
        *(uint32_t*)(sm + G1_BLO + n * G1_ASTR + kp * 4) = lo;
    }
    __syncthreads();

    // ---- compute: warp owns rows [wid*16, wid*16+16), all 19 n-tiles ----
    float c[19][4];
#pragma unroll
    for (int nt = 0; nt < 19; nt++)
#pragma unroll
        for (int q = 0; q < 4; q++) c[nt][q] = 0.f;

    int tq = lane >> 2, tp = lane & 3;
    const char* aArr[3] = {sm + G1_AHI, sm + G1_AHI, sm + G1_ALO};
    const char* bArr[3] = {sm + G1_BHI, sm + G1_BLO, sm + G1_BHI};
#pragma unroll
    for (int p = 0; p < 3; p++) {
        const char* A = aArr[p];
        const char* B = bArr[p];
#pragma unroll
        for (int kc = 0; kc < 8; kc++) {
            int kb = kc * 32 + tp * 4;  // byte offset of k pair
            int ra = (wid * 16 + tq) * G1_ASTR;
            uint32_t a0 = *(const uint32_t*)(A + ra + kb);
            uint32_t a1 = *(const uint32_t*)(A + ra + 8 * G1_ASTR + kb);
            uint32_t a2 = *(const uint32_t*)(A + ra + kb + 16);
            uint32_t a3 = *(const uint32_t*)(A + ra + 8 * G1_ASTR + kb + 16);
#pragma unroll
            for (int nt = 0; nt < 19; nt++) {
                int rb = (nt * 8 + tq) * G1_ASTR;
                uint32_t b0 = *(const uint32_t*)(B + rb + kb);
                uint32_t b1 = *(const uint32_t*)(B + rb + kb + 16);
                mma_bf16(c[nt], a0, a1, a2, a3, b0, b1);
            }
        }
    }

    // ---- epilogue: write xp ----
    int r0 = row0 + wid * 16 + tq, r1 = r0 + 8;
#pragma unroll
    for (int nt = 0; nt < 19; nt++) {
        int col = nt * 8 + tp * 2;
        if (r0 < NN) *(float2*)(g_xp + (size_t)r0 * HF + col) = make_float2(c[nt][0], c[nt][1]);
        if (r1 < NN) *(float2*)(g_xp + (size_t)r1 * HF + col) = make_float2(c[nt][2], c[nt][3]);
    }
}

// ================= attention coefficients =================
__global__ void attn_k(const float* __restrict__ a_s, const float* __restrict__ a_d) {
    __shared__ float ss[HF], sd[HF];
    int t = threadIdx.x;
    if (t < HF) { ss[t] = a_s[t]; sd[t] = a_d[t]; }
    __syncthreads();
    int idx = blockIdx.x * blockDim.x + t;
    if (idx >= NN * HEADS) return;
    int n = idx / HEADS, h = idx % HEADS;
    const float* xr = g_xp + (size_t)n * HF + h * NOUT;
    float vs = 0.f, vd = 0.f;
#pragma unroll
    for (int f = 0; f < NOUT; f++) {
        float x = xr[f];
        vs += x * ss[h * NOUT + f];
        vd += x * sd[h * NOUT + f];
    }
    g_als[idx] = vs;
    g_ald[idx] = vd;
}

// ================= softmax max+sum (thread per dst,head) =================
__global__ void msum_k() {
    int idx = blockIdx.x * blockDim.x + threadIdx.x;
    int d = idx >> 3, h = idx & 7;
    if (d >= NN) return;
    int beg = g_off[d], end = g_off[d + 1];
    float aldv = g_ald[d * HEADS + h];
    float m = -1e30f, s = 0.f;
    float als = g_als[g_ssrc[beg] * HEADS + h];
    for (int e = beg; e < end; e++) {
        float an = 0.f;
        if (e + 1 < end) an = g_als[g_ssrc[e + 1] * HEADS + h];
        float ev = als + aldv;
        ev = ev > 0.f ? ev : SLOPE * ev;
        float mn = fmaxf(m, ev);
        s = s * __expf(m - mn) + __expf(ev - mn);
        m = mn;
        als = an;
    }
    g_mx[d * HEADS + h] = m;
    g_siv[d * HEADS + h] = 1.f / (s + SEPS);
}

// ============ aggregation: msg + bias + layernorm (warp per dst) ==========
__global__ void agg2_k(const float* __restrict__ gb, const float* __restrict__ lg,
                       const float* __restrict__ lb) {
    int gw = (blockIdx.x * blockDim.x + threadIdx.x) >> 5;
    int lane = threadIdx.x & 31;
    if (gw >= NN) return;
    int d = gw;
    int beg = g_off[d], end = g_off[d + 1];

    float aldv = 0.f, mxv = 0.f, siv = 0.f;
    if (lane < HEADS) {
        aldv = g_ald[d * HEADS + lane];
        mxv = g_mx[d * HEADS + lane];
        siv = g_siv[d * HEADS + lane];
    }

    float acc[5] = {0.f, 0.f, 0.f, 0.f, 0.f};
    int s = g_ssrc[beg];
    float als = (lane < HEADS) ? g_als[s * HEADS + lane] : 0.f;
    const float* xr = g_xp + (size_t)s * HF;

    for (int e = beg; e < end; e++) {
        float xv[5];
#pragma unroll
        for (int j = 0; j < 5; j++) {
            int f = lane + 32 * j;
            xv[j] = (f < HF) ? xr[f] : 0.f;
        }
        int sn = 0;
        float an = 0.f;
        if (e + 1 < end) {
            sn = g_ssrc[e + 1];
            an = (lane < HEADS) ? g_als[sn * HEADS + lane] : 0.f;
        }
        float ev = als + aldv;
        ev = ev > 0.f ? ev : SLOPE * ev;
        float a = __expf(ev - mxv) * siv;
#pragma unroll
        for (int j = 0; j < 5; j++) {
            int f = lane + 32 * j;
            int hsrc = (f < HF) ? (f / NOUT) : 0;
            float ah = __shfl_sync(0xffffffffu, a, hsrc);
            acc[j] += ah * xv[j];
        }
        s = sn; als = an;
        xr = g_xp + (size_t)sn * HF;
    }

    float out[5];
    float lsum = 0.f;
#pragma unroll
    for (int j = 0; j < 5; j++) {
        int f = lane + 32 * j;
        if (f < HF) {
            out[j] = acc[j] + gb[f];
            lsum += out[j];
        } else out[j] = 0.f;
    }
#pragma unroll
    for (int o = 16; o > 0; o >>= 1) lsum += __shfl_xor_sync(0xffffffffu, lsum, o);
    float mu = lsum / (float)HF;
    float lvar = 0.f;
#pragma unroll
    for (int j = 0; j < 5; j++) {
        int f = lane + 32 * j;
        if (f < HF) { float dv = out[j] - mu; lvar += dv * dv; }
    }
#pragma unroll
    for (int o = 16; o > 0; o >>= 1) lvar += __shfl_xor_sync(0xffffffffu, lvar, o);
    float inv = rsqrtf(lvar / (float)HF + 1e-5f);
#pragma unroll
    for (int j = 0; j < 5; j++) {
        int f = lane + 32 * j;
        if (f < HF) g_u[d * HF + f] = (out[j] - mu) * inv * lg[f] + lb[f];
    }
}

// ====== GEMM2: h_new = 2h + u[N,152] @ fW[152,128] + fb, mma.sync bf16 =====
// K padded 152 -> 160 (10 k-chunks). smem row stride 168 bf16 (336B).
#define G2_ASTR 336
#define G2_AHI 0
#define G2_ALO (G2_AHI + 128 * G2_ASTR)            // 43008
#define G2_BHI (G2_ALO + 128 * G2_ASTR)            // 86016
#define G2_BLO (G2_BHI + 128 * G2_ASTR)            // 129024
#define G2_SMEM (G2_BLO + 128 * G2_ASTR)           // 172032

__global__ __launch_bounds__(256, 1) void gemm2_k(const float* __restrict__ fW,
                                                  const float* __restrict__ fb,
                                                  float* dst) {
    extern __shared__ char sm[];
    int t = threadIdx.x, lane = t & 31, wid = t >> 5;
    int row0 = blockIdx.x * 128;
    float* o = dst ? dst : g_h;

    // ---- A fill: 128 rows x 80 col-pairs (pad cp 76..79 zero) ----
    for (int i = t; i < 128 * 80; i += 256) {
        int r = i / 80, cp = i % 80;
        int gr = row0 + r;
        float2 v = (gr < NN && cp < 76) ? *(const float2*)(g_u + (size_t)gr * HF + 2 * cp)
                                        : make_float2(0.f, 0.f);
        uint32_t hi, lo;
        split_bf16(v.x, v.y, hi, lo);
        *(uint32_t*)(sm + G2_AHI + r * G2_ASTR + cp * 4) = hi;
        *(uint32_t*)(sm + G2_ALO + r * G2_ASTR + cp * 4) = lo;
    }
    // ---- B fill: Bs[n][kp] = (fW[2kp][n], fW[2kp+1][n]), pad kp 76..79 ----
    for (int i = t; i < 80 * HID; i += 256) {
        int kp = i / HID, n = i % HID;
        uint32_t hi = 0, lo = 0;
        if (kp < 76) {
            float w0 = fW[(2 * kp) * HID + n];
            float w1 = fW[(2 * kp + 1) * HID + n];
            split_bf16(w0, w1, hi, lo);
        }
        *(uint32_t*)(sm + G2_BHI + n * G2_ASTR + kp * 4) = hi;
        *(uint32_t*)(sm + G2_BLO + n * G2_ASTR + kp * 4) = lo;
    }
    __syncthreads();

    float c[16][4];
#pragma unroll
    for (int nt = 0; nt < 16; nt++)
#pragma unroll
        for (int q = 0; q < 4; q++) c[nt][q] = 0.f;

    int tq = lane >> 2, tp = lane & 3;
    const char* aArr[3] = {sm + G2_AHI, sm + G2_AHI, sm + G2_ALO};
    const char* bArr[3] = {sm + G2_BHI, sm + G2_BLO, sm + G2_BHI};
#pragma unroll
    for (int p = 0; p < 3; p++) {
        const char* A = aArr[p];
        const char* B = bArr[p];
#pragma unroll
        for (int kc = 0; kc < 10; kc++) {
            int kb = kc * 32 + tp * 4;
            int ra = (wid * 16 + tq) * G2_ASTR;
            uint32_t a0 = *(const uint32_t*)(A + ra + kb);
            uint32_t a1 = *(const uint32_t*)(A + ra + 8 * G2_ASTR + kb);
            uint32_t a2 = *(const uint32_t*)(A + ra + kb + 16);
            uint32_t a3 = *(const uint32_t*)(A + ra + 8 * G2_ASTR + kb + 16);
#pragma unroll
            for (int nt = 0; nt < 16; nt++) {
                int rb = (nt * 8 + tq) * G2_ASTR;
                uint32_t b0 = *(const uint32_t*)(B + rb + kb);
                uint32_t b1 = *(const uint32_t*)(B + rb + kb + 16);
                mma_bf16(c[nt], a0, a1, a2, a3, b0, b1);
            }
        }
    }

    // ---- epilogue: out = 2h + c + fb ----
    int r0 = row0 + wid * 16 + tq, r1 = r0 + 8;
#pragma unroll
    for (int nt = 0; nt < 16; nt++) {
        int col = nt * 8 + tp * 2;
        float2 fbv = *(const float2*)(fb + col);
        if (r0 < NN) {
            float2 hv = *(const float2*)(g_h + (size_t)r0 * HID + col);
            *(float2*)(o + (size_t)r0 * HID + col) =
                make_float2(2.f * hv.x + c[nt][0] + fbv.x, 2.f * hv.y + c[nt][1] + fbv.y);
        }
        if (r1 < NN) {
            float2 hv = *(const float2*)(g_h + (size_t)r1 * HID + col);
            *(float2*)(o + (size_t)r1 * HID + col) =
                make_float2(2.f * hv.x + c[nt][2] + fbv.x, 2.f * hv.y + c[nt][3] + fbv.y);
        }
    }
}

// ================= launch =================
extern "C" void kernel_launch(void* const* d_in, const int* in_sizes, int n_in,
                              void* d_out, int out_size) {
    const int* z = (const int*)d_in[0];
    const int* ei = (const int*)d_in[2];
    const float* emb = (const float*)d_in[3];
    const float* gat_W = (const float*)d_in[4];
    const float* gat_b = (const float*)d_in[5];
    const float* a_src = (const float*)d_in[6];
    const float* a_dst = (const float*)d_in[7];
    const float* ln_g = (const float*)d_in[8];
    const float* ln_b = (const float*)d_in[9];
    const float* ff_W = (const float*)d_in[10];
    const float* ff_b = (const float*)d_in[11];
    float* outp = (float*)d_out;

    const int* row = ei;
    const int* col = ei + EE;

    cudaFuncSetAttribute(gemm1_k, cudaFuncAttributeMaxDynamicSharedMemorySize, G1_SMEM);
    cudaFuncSetAttribute(gemm2_k, cudaFuncAttributeMaxDynamicSharedMemorySize, G2_SMEM);

    const int GB = (NN + 127) / 128;  // 391 tiles

    embed_k<<<(NN * 32 + 255) / 256, 256>>>(z, emb);       // 1
    hist_k<<<(EE + 255) / 256, 256>>>(col);                // 2
    scan1_k<<<NB, 1024>>>();                               // 3
    scan2_k<<<1, 32>>>();                                  // 4
    scan3_k<<<(NN + 255) / 256, 256>>>();                  // 5
    gemm1_k<<<GB, 256, G1_SMEM>>>(gat_W);                  // 6 <- profiled slot
    attn_k<<<(NN * HEADS + 255) / 256, 256>>>(a_src, a_dst);
    scatter_k<<<(ET + 255) / 256, 256>>>(row, col);
    msum_k<<<(NN * HEADS + 255) / 256, 256>>>();
    agg2_k<<<(NN + 7) / 8, 256>>>(gat_b, ln_g, ln_b);
    gemm2_k<<<GB, 256, G2_SMEM>>>(ff_W, ff_b, nullptr);

    for (int b = 1; b < 3; b++) {
        gemm1_k<<<GB, 256, G1_SMEM>>>(gat_W + b * HID * HF);
        attn_k<<<(NN * HEADS + 255) / 256, 256>>>(a_src + b * HF, a_dst + b * HF);
        msum_k<<<(NN * HEADS + 255) / 256, 256>>>();
        agg2_k<<<(NN + 7) / 8, 256>>>(gat_b + b * HF, ln_g + b * HF, ln_b + b * HF);
        gemm2_k<<<GB, 256, G2_SMEM>>>(ff_W + b * HF * HID, ff_b + b * HID,
                                      (b == 2) ? outp : nullptr);
    }
}